// round 11
// baseline (speedup 1.0000x reference)
#include <cuda_runtime.h>
#include <cuda_fp16.h>
#include <math.h>
#include <stdint.h>

#define NN   40960
#define SS   4096
#define EE   81920
#define DD   64
#define HH   100
#define FIN  321
#define VV   50000

// ---------------- scratch (device globals; no allocation allowed) ----------------
__device__ float    g_x[NN * FIN];
__device__ float    g_xl[SS * FIN];
__device__ float    g_h[NN * HH];
__device__ float    g_msg[NN * HH];
__device__ float    g_gi[NN * 3 * HH];
__device__ float    g_gh[NN * 3 * HH];
__device__ int      g_deg[NN];
__device__ float    g_dinv[NN];
__device__ int      g_lastidx[SS];
__device__ float    g_last[SS * HH];
__device__ float    g_g1[NN * HH];
__device__ float    g_gate[NN];
__device__ float    g_w[NN];
__device__ unsigned g_gmax[SS];
__device__ float    g_wsum[SS];
__device__ float    g_pooled[SS * HH];

// ---------------- fp16 mma.sync (plain HMMA path, sm_70+ PTX) ----------------
// m16n8k16 row.col f32.f16.f16.f32 fragment layout (g = lane>>2, tg = lane&3):
//   A reg0 = (row g,   k 2tg..2tg+1)   reg1 = (row g+8, k 2tg..2tg+1)
//   A reg2 = (row g,   k 2tg+8..+9)    reg3 = (row g+8, k 2tg+8..+9)
//   B reg0 = (k 2tg..2tg+1, col g)     reg1 = (k 2tg+8..+9, col g)
//   C c0/c1 = (row g, col 2tg/2tg+1)   c2/c3 = (row g+8, same cols)
__device__ __forceinline__ void mma_16n8k16_f16(float* d,
                                                const uint32_t* a, const uint32_t* b) {
    asm volatile(
        "mma.sync.aligned.m16n8k16.row.col.f32.f16.f16.f32 "
        "{%0, %1, %2, %3}, {%4, %5, %6, %7}, {%8, %9}, {%0, %1, %2, %3};"
        : "+f"(d[0]), "+f"(d[1]), "+f"(d[2]), "+f"(d[3])
        : "r"(a[0]), "r"(a[1]), "r"(a[2]), "r"(a[3]), "r"(b[0]), "r"(b[1]));
}

// ---------------- helpers ----------------
__device__ __forceinline__ unsigned enc_f(float f) {
    unsigned u = __float_as_uint(f);
    return (u & 0x80000000u) ? ~u : (u | 0x80000000u);
}
__device__ __forceinline__ float dec_f(unsigned e) {
    return (e & 0x80000000u) ? __uint_as_float(e ^ 0x80000000u) : __uint_as_float(~e);
}
__device__ __forceinline__ float fast_sigmoid(float x) {
    return 1.f / (1.f + __expf(-x));
}
__device__ __forceinline__ float fast_tanh(float x) {
    float t = __expf(-2.f * fabsf(x));
    float y = (1.f - t) / (1.f + t);
    return copysignf(y, x);
}
// split v into fp16 hi + fp16 lo pair words
__device__ __forceinline__ void split_pack(float v0, float v1,
                                           uint32_t& whi, uint32_t& wlo) {
    __half h0 = __float2half_rn(v0), h1 = __float2half_rn(v1);
    float  l0 = v0 - __half2float(h0), l1 = v1 - __half2float(h1);
    __half2 hh = __halves2half2(h0, h1);
    __half2 ll = __floats2half2_rn(l0, l1);
    whi = *(uint32_t*)&hh;
    wlo = *(uint32_t*)&ll;
}

// ---------------- init / zero ----------------
__global__ void k_init_small() {
    int i = blockIdx.x * blockDim.x + threadIdx.x;
    if (i < NN) g_deg[i] = 0;
    if (i < SS) { g_lastidx[i] = -1; g_gmax[i] = 0u; g_wsum[i] = 0.f; }
}
__global__ void k_zero_big() {
    int i = blockIdx.x * blockDim.x + threadIdx.x;
    if (i < NN * HH) g_msg[i] = 0.f;
    if (i < SS * HH) g_pooled[i] = 0.f;
}

// ---------------- node feature gather: x[n, 0..320] ----------------
__global__ void k_gather_x(const float* __restrict__ price,
                           const int* __restrict__ cat, const int* __restrict__ sub,
                           const int* __restrict__ elem, const int* __restrict__ brand,
                           const int* __restrict__ pid,
                           const float* __restrict__ ecat, const float* __restrict__ esub,
                           const float* __restrict__ eelem, const float* __restrict__ ebrand,
                           const float* __restrict__ eitem) {
    int n = blockIdx.x;
    int j = threadIdx.x;
    if (j >= FIN) return;
    float v;
    if (j == 0) {
        v = price[n];
    } else {
        int s = (j - 1) >> 6;
        int o = (j - 1) & 63;
        const float* tab;
        int idx;
        switch (s) {
            case 0:  tab = ecat;   idx = cat[n];   break;
            case 1:  tab = esub;   idx = sub[n];   break;
            case 2:  tab = eelem;  idx = elem[n];  break;
            case 3:  tab = ebrand; idx = brand[n]; break;
            default: tab = eitem;  idx = pid[n];   break;
        }
        v = tab[idx * DD + o];
    }
    g_x[n * FIN + j] = v;
}

// ========== split-fp16 HMMA GEMM: C = A[M,K] @ B[K,Nn] + bias, optional relu ==========
// Full fp32-equivalent precision: A = Ah+Al, B = Bh+Bl (fp16 hi + residual);
// C ≈ AhBh + AhBl + AlBh (drops only AlBl ~ 2^-22).
// CTA tile 128x128, warp grid 2x4 (warp tile 64x32), K chunked by 112 (7 MMA k-steps).
// smem half-tiles stride 120 halves = 60 words; fragment bank = (28g+tg)%32 conflict-free.
#define KC   112
#define KCW  56                        // valid word-cols per chunk
#define STW  60                        // word stride per row
#define HG_SMEM (4 * 128 * STW * 4 + 512)   /* 123392 bytes */

__global__ void __launch_bounds__(256)
k_hgemm(const float* __restrict__ A, const float* __restrict__ B,
        const float* __restrict__ bias, float* __restrict__ C,
        int M, int Nn, int K, int relu) {
    extern __shared__ __align__(16) char smraw[];
    uint32_t* AsH = (uint32_t*)smraw;
    uint32_t* AsL = AsH + 128 * STW;
    uint32_t* BsH = AsL + 128 * STW;
    uint32_t* BsL = BsH + 128 * STW;
    float* biasS  = (float*)(BsL + 128 * STW);
    int tid = threadIdx.x;
    int lane = tid & 31, wid = tid >> 5;
    int n0 = blockIdx.x * 128, m0 = blockIdx.y * 128;

    if (tid < 128) biasS[tid] = (n0 + tid < Nn) ? bias[n0 + tid] : 0.f;

    int wm = wid >> 2, wn = wid & 3;
    int g = lane >> 2, tg = lane & 3;

    float acc[4][4][4];
#pragma unroll
    for (int mi = 0; mi < 4; mi++)
#pragma unroll
        for (int ni = 0; ni < 4; ni++)
#pragma unroll
            for (int j = 0; j < 4; j++) acc[mi][ni][j] = 0.f;

    int nch = (K + KC - 1) / KC;
    for (int ch = 0; ch < nch; ch++) {
        int k0 = ch * KC;
        __syncthreads();
        // A tile: 128 rows x 56 k-pair words (zero-padded past K / M)
        for (int i = tid; i < 128 * KCW; i += 256) {
            int r = i / KCW, kp = i - r * KCW;
            int gk = k0 + 2 * kp, gr = m0 + r;
            float v0 = 0.f, v1 = 0.f;
            if (gr < M) {
                if (gk < K)     v0 = A[(size_t)gr * K + gk];
                if (gk + 1 < K) v1 = A[(size_t)gr * K + gk + 1];
            }
            uint32_t whi, wlo;
            split_pack(v0, v1, whi, wlo);
            AsH[r * STW + kp] = whi;
            AsL[r * STW + kp] = wlo;
        }
        // B tile (transposed to [n][k]): coalesced over n
        for (int i = tid; i < 128 * KCW; i += 256) {
            int n = i & 127, kp = i >> 7;
            int gn = n0 + n, gk = k0 + 2 * kp;
            float v0 = 0.f, v1 = 0.f;
            if (gn < Nn) {
                if (gk < K)     v0 = B[(size_t)gk * Nn + gn];
                if (gk + 1 < K) v1 = B[(size_t)(gk + 1) * Nn + gn];
            }
            uint32_t whi, wlo;
            split_pack(v0, v1, whi, wlo);
            BsH[n * STW + kp] = whi;
            BsL[n * STW + kp] = wlo;
        }
        __syncthreads();

#pragma unroll
        for (int ks = 0; ks < 7; ks++) {
            int kw = ks * 8;
            uint32_t afH[4][4], afL[4][4], bfH[4][2], bfL[4][2];
#pragma unroll
            for (int mi = 0; mi < 4; mi++) {
                int r0 = wm * 64 + mi * 16 + g;
                const uint32_t* apH = &AsH[r0 * STW + kw + tg];
                const uint32_t* apL = &AsL[r0 * STW + kw + tg];
                afH[mi][0] = apH[0];            afH[mi][1] = apH[8 * STW];
                afH[mi][2] = apH[4];            afH[mi][3] = apH[8 * STW + 4];
                afL[mi][0] = apL[0];            afL[mi][1] = apL[8 * STW];
                afL[mi][2] = apL[4];            afL[mi][3] = apL[8 * STW + 4];
            }
#pragma unroll
            for (int ni = 0; ni < 4; ni++) {
                int nb = wn * 32 + ni * 8 + g;
                const uint32_t* bpH = &BsH[nb * STW + kw + tg];
                const uint32_t* bpL = &BsL[nb * STW + kw + tg];
                bfH[ni][0] = bpH[0];            bfH[ni][1] = bpH[4];
                bfL[ni][0] = bpL[0];            bfL[ni][1] = bpL[4];
            }
#pragma unroll
            for (int mi = 0; mi < 4; mi++)
#pragma unroll
                for (int ni = 0; ni < 4; ni++) {
                    mma_16n8k16_f16(acc[mi][ni], afH[mi], bfH[ni]);
                    mma_16n8k16_f16(acc[mi][ni], afH[mi], bfL[ni]);
                    mma_16n8k16_f16(acc[mi][ni], afL[mi], bfH[ni]);
                }
        }
    }

    // epilogue (M is always a multiple of 128 here; Nn even, pairs never straddle)
#pragma unroll
    for (int mi = 0; mi < 4; mi++) {
        int r = m0 + wm * 64 + mi * 16 + g;
        size_t rb0 = (size_t)r * Nn;
        size_t rb1 = (size_t)(r + 8) * Nn;
#pragma unroll
        for (int ni = 0; ni < 4; ni++) {
            int cn = wn * 32 + ni * 8 + 2 * tg;
            int gn = n0 + cn;
            if (gn < Nn) {
                float bx = biasS[cn], by = biasS[cn + 1];
                float v00 = acc[mi][ni][0] + bx, v01 = acc[mi][ni][1] + by;
                float v10 = acc[mi][ni][2] + bx, v11 = acc[mi][ni][3] + by;
                if (relu) {
                    v00 = fmaxf(v00, 0.f); v01 = fmaxf(v01, 0.f);
                    v10 = fmaxf(v10, 0.f); v11 = fmaxf(v11, 0.f);
                }
                *(float2*)&C[rb0 + gn] = make_float2(v00, v01);
                *(float2*)&C[rb1 + gn] = make_float2(v10, v11);
            }
        }
    }
}

// ---------------- degree + inverse ----------------
__global__ void k_deg(const int* __restrict__ eidx) {
    int e = blockIdx.x * blockDim.x + threadIdx.x;
    if (e < EE) atomicAdd(&g_deg[eidx[EE + e]], 1);
}
__global__ void k_dinv() {
    int n = blockIdx.x * blockDim.x + threadIdx.x;
    if (n < NN) g_dinv[n] = (g_deg[n] > 0) ? (1.f / (float)g_deg[n]) : 0.f;
}

// ---------------- edge scatter: msg[dst] += h[src] ----------------
__global__ void k_scatter(const int* __restrict__ eidx) {
    int e = blockIdx.x;
    int d = threadIdx.x;
    if (d >= HH) return;
    int s = eidx[e];
    int t = eidx[EE + e];
    atomicAdd(&g_msg[t * HH + d], g_h[s * HH + d]);
}
__global__ void k_scale_msg() {
    int i = blockIdx.x * blockDim.x + threadIdx.x;
    if (i < NN * HH) g_msg[i] *= g_dinv[i / HH];
}

// ---------------- GRU cell elementwise ----------------
__global__ void k_gru() {
    int i = blockIdx.x * blockDim.x + threadIdx.x;
    if (i >= NN * HH) return;
    int n = i / HH, j = i % HH;
    const float* gi = g_gi + n * 3 * HH;
    const float* gh = g_gh + n * 3 * HH;
    float r  = fast_sigmoid(gi[j] + gh[j]);
    float z  = fast_sigmoid(gi[HH + j] + gh[HH + j]);
    float nn = fast_tanh(gi[2 * HH + j] + r * gh[2 * HH + j]);
    float h  = g_h[i];
    g_h[i] = (1.f - z) * nn + z * h;
}

// ---------------- last index per session + gather ----------------
__global__ void k_lastidx(const int* __restrict__ batch) {
    int n = blockIdx.x * blockDim.x + threadIdx.x;
    if (n < NN) atomicMax(&g_lastidx[batch[n]], n);
}
__global__ void k_gather_xl() {
    int s = blockIdx.x;
    int j = threadIdx.x;
    if (j >= FIN) return;
    g_xl[s * FIN + j] = g_x[g_lastidx[s] * FIN + j];
}
__global__ void k_addlast(const int* __restrict__ batch) {
    int i = blockIdx.x * blockDim.x + threadIdx.x;
    if (i >= NN * HH) return;
    g_h[i] += g_last[batch[i / HH] * HH + i % HH];
}

// ---------------- attention gate ----------------
__global__ void k_gate(const float* __restrict__ wg2, const float* __restrict__ bg2,
                       const int* __restrict__ batch) {
    int w = (blockIdx.x * blockDim.x + threadIdx.x) >> 5;
    int lane = threadIdx.x & 31;
    if (w >= NN) return;
    const float* row = g_g1 + w * HH;
    float s = 0.f;
    for (int k = lane; k < HH; k += 32) s += row[k] * wg2[k];
#pragma unroll
    for (int o = 16; o; o >>= 1) s += __shfl_xor_sync(0xffffffffu, s, o);
    if (lane == 0) {
        float g = s + bg2[0];
        g_gate[w] = g;
        atomicMax(&g_gmax[batch[w]], enc_f(g));
    }
}
__global__ void k_softw(const int* __restrict__ batch) {
    int n = blockIdx.x * blockDim.x + threadIdx.x;
    if (n >= NN) return;
    int b = batch[n];
    float wv = __expf(g_gate[n] - dec_f(g_gmax[b]));
    g_w[n] = wv;
    atomicAdd(&g_wsum[b], wv);
}
__global__ void k_pool(const int* __restrict__ batch) {
    int n = blockIdx.x;
    int d = threadIdx.x;
    if (d >= HH) return;
    int b = batch[n];
    float alpha = g_w[n] / g_wsum[b];
    atomicAdd(&g_pooled[b * HH + d], alpha * g_h[n * HH + d]);
}

// ================= FC via fp16 mma.sync m16n8k16 (native HMMA path) =================
// out[4096,50000] = pooled @ W_fc + b_fc  (fp16 inputs, fp32 accumulate)
#define FKH 120
#define FC_SMEM_H (128 * FKH * 2 * 2 + 512)   /* 61952 bytes */

__global__ void __launch_bounds__(256)
k_fc(const float* __restrict__ pooled, const float* __restrict__ W,
     const float* __restrict__ bias, float* __restrict__ C) {
    extern __shared__ __align__(16) char smraw[];
    __half*   BsH  = (__half*)smraw;                       // [128][FKH]
    uint32_t* Bs32 = (uint32_t*)smraw;                     // word view, stride 60
    uint32_t* As32 = (uint32_t*)(smraw + 128 * FKH * 2);   // word view, stride 60
    float*    biasS = (float*)(smraw + 2 * 128 * FKH * 2); // [128]
    int tid = threadIdx.x;
    int lane = tid & 31, wid = tid >> 5;
    int n0 = blockIdx.x * 128;
    int m_begin = blockIdx.y * 16;

    // zero both half tiles (covers K-pad cols and out-of-range N rows)
    for (int i = tid; i < 2 * 128 * (FKH / 2); i += 256) ((uint32_t*)smraw)[i] = 0u;
    if (tid < 128) biasS[tid] = (n0 + tid < VV) ? bias[n0 + tid] : 0.f;
    __syncthreads();

    // load B panel: W[k][n] -> BsH[n][k], coalesced over n, fp32 -> fp16
    for (int i = tid; i < HH * 128; i += 256) {
        int k = i >> 7, n = i & 127;
        int gn = n0 + n;
        if (gn < VV) BsH[n * FKH + k] = __float2half_rn(W[(size_t)k * VV + gn]);
    }

    int wm = wid >> 2, wn = wid & 3;
    int g = lane >> 2, tg = lane & 3;

    for (int it = 0; it < 16; it++) {
        int m0 = (m_begin + it) * 128;
        for (int p = tid; p < 128 * (HH / 2); p += 256) {
            int r = p / (HH / 2), kp = p - r * (HH / 2);
            float2 v = *(const float2*)&pooled[(size_t)(m0 + r) * HH + 2 * kp];
            __half2 h2 = __floats2half2_rn(v.x, v.y);
            As32[r * (FKH / 2) + kp] = *(uint32_t*)&h2;
        }
        __syncthreads();

        float acc[4][4][4];
#pragma unroll
        for (int mi = 0; mi < 4; mi++)
#pragma unroll
            for (int ni = 0; ni < 4; ni++)
#pragma unroll
                for (int j = 0; j < 4; j++) acc[mi][ni][j] = 0.f;

#pragma unroll
        for (int ks = 0; ks < 7; ks++) {
            int kw = ks * 8;
            uint32_t af[4][4], bf[4][2];
#pragma unroll
            for (int mi = 0; mi < 4; mi++) {
                int r0 = wm * 64 + mi * 16 + g;
                const uint32_t* ap = &As32[r0 * 60 + kw + tg];
                af[mi][0] = ap[0];
                af[mi][1] = ap[8 * 60];
                af[mi][2] = ap[4];
                af[mi][3] = ap[8 * 60 + 4];
            }
#pragma unroll
            for (int ni = 0; ni < 4; ni++) {
                int nb = wn * 32 + ni * 8 + g;
                const uint32_t* bp = &Bs32[nb * 60 + kw + tg];
                bf[ni][0] = bp[0];
                bf[ni][1] = bp[4];
            }
#pragma unroll
            for (int mi = 0; mi < 4; mi++)
#pragma unroll
                for (int ni = 0; ni < 4; ni++)
                    mma_16n8k16_f16(acc[mi][ni], af[mi], bf[ni]);
        }

#pragma unroll
        for (int mi = 0; mi < 4; mi++) {
            int r = m0 + wm * 64 + mi * 16 + g;
            size_t rb0 = (size_t)r * VV;
            size_t rb1 = (size_t)(r + 8) * VV;
#pragma unroll
            for (int ni = 0; ni < 4; ni++) {
                int cn = wn * 32 + ni * 8 + 2 * tg;
                int gn = n0 + cn;
                if (gn < VV) {
                    float bx = biasS[cn], by = biasS[cn + 1];
                    *(float2*)&C[rb0 + gn] = make_float2(acc[mi][ni][0] + bx,
                                                         acc[mi][ni][1] + by);
                    *(float2*)&C[rb1 + gn] = make_float2(acc[mi][ni][2] + bx,
                                                         acc[mi][ni][3] + by);
                }
            }
        }
        __syncthreads();
    }
}

// ---------------- launch ----------------
extern "C" void kernel_launch(void* const* d_in, const int* in_sizes, int n_in,
                              void* d_out, int out_size) {
    const float* price    = (const float*)d_in[0];
    const int*   category = (const int*)d_in[1];
    const int*   sub      = (const int*)d_in[2];
    const int*   elem     = (const int*)d_in[3];
    const int*   brand    = (const int*)d_in[4];
    const int*   pid      = (const int*)d_in[5];
    const int*   eidx     = (const int*)d_in[6];
    const int*   batch    = (const int*)d_in[7];
    const float* ecat     = (const float*)d_in[8];
    const float* esub     = (const float*)d_in[9];
    const float* eelem    = (const float*)d_in[10];
    const float* ebrand   = (const float*)d_in[11];
    const float* eitem    = (const float*)d_in[12];
    const float* W_msg    = (const float*)d_in[13];
    const float* b_msg    = (const float*)d_in[14];
    const float* W_ih     = (const float*)d_in[15];
    const float* W_hh     = (const float*)d_in[16];
    const float* b_ih     = (const float*)d_in[17];
    const float* b_hh     = (const float*)d_in[18];
    const float* W_last   = (const float*)d_in[19];
    const float* b_last   = (const float*)d_in[20];
    const float* W_g1     = (const float*)d_in[21];
    const float* b_g1     = (const float*)d_in[22];
    const float* W_g2     = (const float*)d_in[23];
    const float* b_g2     = (const float*)d_in[24];
    const float* W_fc     = (const float*)d_in[25];
    const float* b_fc     = (const float*)d_in[26];
    float* out = (float*)d_out;

    float *p_x, *p_xl, *p_h, *p_msg, *p_gi, *p_gh, *p_last, *p_g1, *p_pooled;
    cudaGetSymbolAddress((void**)&p_x,      g_x);
    cudaGetSymbolAddress((void**)&p_xl,     g_xl);
    cudaGetSymbolAddress((void**)&p_h,      g_h);
    cudaGetSymbolAddress((void**)&p_msg,    g_msg);
    cudaGetSymbolAddress((void**)&p_gi,     g_gi);
    cudaGetSymbolAddress((void**)&p_gh,     g_gh);
    cudaGetSymbolAddress((void**)&p_last,   g_last);
    cudaGetSymbolAddress((void**)&p_g1,     g_g1);
    cudaGetSymbolAddress((void**)&p_pooled, g_pooled);

    cudaFuncSetAttribute(k_fc,    cudaFuncAttributeMaxDynamicSharedMemorySize, FC_SMEM_H);
    cudaFuncSetAttribute(k_hgemm, cudaFuncAttributeMaxDynamicSharedMemorySize, HG_SMEM);

    // init scratch
    k_init_small<<<(NN + 255) / 256, 256>>>();
    k_zero_big<<<(NN * HH + 255) / 256, 256>>>();

    // node features
    k_gather_x<<<NN, 352>>>(price, category, sub, elem, brand, pid,
                            ecat, esub, eelem, ebrand, eitem);

    // h0 = x @ W_msg + b_msg   (split-fp16 HMMA)
    {
        dim3 g(1, NN / 128);
        k_hgemm<<<g, 256, HG_SMEM>>>(p_x, W_msg, b_msg, p_h, NN, HH, FIN, 0);
    }

    // degrees
    k_deg<<<(EE + 255) / 256, 256>>>(eidx);
    k_dinv<<<(NN + 255) / 256, 256>>>();

    // mean aggregation
    k_scatter<<<EE, 128>>>(eidx);
    k_scale_msg<<<(NN * HH + 255) / 256, 256>>>();

    // GRU gates (split-fp16 HMMA)
    {
        dim3 g((3 * HH + 127) / 128, NN / 128);
        k_hgemm<<<g, 256, HG_SMEM>>>(p_msg, W_ih, b_ih, p_gi, NN, 3 * HH, HH, 0);
        k_hgemm<<<g, 256, HG_SMEM>>>(p_h,   W_hh, b_hh, p_gh, NN, 3 * HH, HH, 0);
    }
    k_gru<<<(NN * HH + 255) / 256, 256>>>();

    // last node per session
    k_lastidx<<<(NN + 255) / 256, 256>>>(batch);
    k_gather_xl<<<SS, 352>>>();
    {
        dim3 g(1, SS / 128);
        k_hgemm<<<g, 256, HG_SMEM>>>(p_xl, W_last, b_last, p_last, SS, HH, FIN, 0);
    }
    k_addlast<<<(NN * HH + 255) / 256, 256>>>(batch);

    // attention gate MLP (split-fp16 HMMA, relu)
    {
        dim3 g(1, NN / 128);
        k_hgemm<<<g, 256, HG_SMEM>>>(p_h, W_g1, b_g1, p_g1, NN, HH, HH, 1);
    }
    k_gate<<<(NN * 32 + 255) / 256, 256>>>(W_g2, b_g2, batch);
    k_softw<<<(NN + 255) / 256, 256>>>(batch);
    k_pool<<<NN, 128>>>(batch);

    // final scoring: fp16 mma.sync m16n8k16
    {
        dim3 g((VV + 127) / 128, 2);
        k_fc<<<g, 256, FC_SMEM_H>>>(p_pooled, W_fc, b_fc, out);
    }
}